// round 5
// baseline (speedup 1.0000x reference)
#include <cuda_runtime.h>

#define Nn 80
#define Fh 64
#define Hh 256
#define Zz 128
#define OFFS 3160
#define Eg 800
#define ITERS 50
#define NB 16
#define AB 5       // a-rows per CTA
#define NT 512
#define XP 82      // padded SMEM row stride (floats); 41 8B-granules, gcd(41,32)=1

// ---------------- device scratch (static, allocation-free) ----------------
__device__ float g_Ag[Nn*Nn];
__device__ float g_T[Nn*Hh];
__device__ float g_U[Nn*Hh];
__device__ float g_he[Hh];
__device__ float g_B[Nn*Nn];
__device__ float g_A[Nn*Nn];
__device__ float g_X0[Nn*Nn];
__device__ float g_X1[Nn*Nn];
__device__ unsigned g_bar;
__device__ unsigned g_maxbits[ITERS+1];

// ---------------- barrier primitives (release/acquire, no SC fences) ------
__device__ __forceinline__ void bar_arrive() {
    asm volatile("red.release.gpu.add.u32 [%0], %1;" :: "l"(&g_bar), "r"(1u) : "memory");
}
__device__ __forceinline__ unsigned bar_ld() {
    unsigned v;
    asm volatile("ld.acquire.gpu.u32 %0, [%1];" : "=r"(v) : "l"(&g_bar) : "memory");
    return v;
}
__device__ __forceinline__ void red_max_relaxed(unsigned* p, unsigned v) {
    asm volatile("red.relaxed.gpu.max.u32 [%0], %1;" :: "l"(p), "r"(v) : "memory");
}

// ============ launch 1: setup (deg, Ag, A', B=0, bar reset) + x@W1 ========
__global__ void k_setup_xw1(const float* __restrict__ x, const int* __restrict__ ei,
                            const int* __restrict__ adj, const float* __restrict__ W1) {
    __shared__ int   se[2*Eg];
    __shared__ int   cnt[Nn];
    __shared__ int   acnt[Nn];
    __shared__ float dinv[Nn];
    __shared__ float xr[Fh];
    int t = threadIdx.x, row = blockIdx.x;

    if (row == 0 && t <= ITERS + 1) {
        if (t == 0) g_bar = 0u;
        if (t >= 1) g_maxbits[t-1] = 0u;
    }
    for (int e = t; e < 2*Eg; e += 256) se[e] = ei[e];
    if (t < Nn) { cnt[t] = 1; acnt[t] = 0; }
    for (int k = t; k < Fh; k += 256) xr[k] = x[row*Fh + k];
    __syncthreads();
    for (int e = t; e < Eg; e += 256) atomicAdd(&cnt[se[Eg+e]], 1);
    for (int e = t; e < Eg; e += 256)
        if (se[Eg+e] == row) atomicAdd(&acnt[se[e]], 1);   // int atomics: deterministic
    __syncthreads();
    if (t < Nn) dinv[t] = rsqrtf((float)cnt[t]);
    __syncthreads();
    if (t < Nn) {
        float v = (float)acnt[t] * dinv[t] * dinv[row];
        if (t == row) v += dinv[row] * dinv[row];          // self loop
        g_Ag[row*Nn + t] = v;
        g_A[row*Nn + t] = (row != t && ((adj[row*Nn+t] | adj[t*Nn+row]) != 0)) ? 1.f : 0.f;
        g_B[row*Nn + t] = 0.f;
    }
    float acc = 0.f;
    #pragma unroll 8
    for (int k = 0; k < Fh; ++k) acc += xr[k] * W1[k*Hh + t];
    g_T[row*Hh + t] = acc;
}

// ============ launches 2 & 4: U = Ag @ T + bias ===========================
__global__ void k_agg(const float* __restrict__ bias) {
    __shared__ float ar[Nn];
    int t = threadIdx.x, row = blockIdx.x;
    if (t < Nn) ar[t] = g_Ag[row*Nn + t];
    __syncthreads();
    float acc = bias[t];
    #pragma unroll 8
    for (int j = 0; j < Nn; ++j) acc += ar[j] * g_T[j*Hh + t];
    g_U[row*Hh + t] = acc;
}

// ============ launch 3: BN1 + ReLU + H@W2 (BN recomputed per CTA) =========
__global__ void k_bn_xw2(const float* __restrict__ g1, const float* __restrict__ bt1,
                         const float* __restrict__ W2) {
    __shared__ float Hrow[Hh];
    int t = threadIdx.x, row = blockIdx.x;
    float s = 0.f, s2 = 0.f, urow = 0.f;
    for (int i = 0; i < Nn; ++i) {
        float u = g_U[i*Hh + t];
        s += u; s2 += u*u;
        if (i == row) urow = u;
    }
    float m = s * (1.f/Nn);
    float v = s2 * (1.f/Nn) - m*m;
    float sc = g1[t] * rsqrtf(fmaxf(v, 0.f) + 1e-5f);
    Hrow[t] = fmaxf((urow - m)*sc + bt1[t], 0.f);
    __syncthreads();
    float acc = 0.f;
    #pragma unroll 8
    for (int k = 0; k < Hh; ++k) acc += Hrow[k] * W2[k*Hh + t];
    g_T[row*Hh + t] = acc;
}

// ============ launch 5: BN2 + ReLU + pool + reparam + decoder hidden ======
__global__ void k_head(const float* __restrict__ g2, const float* __restrict__ bt2,
                       const float* __restrict__ Wmu, const float* __restrict__ bmu,
                       const float* __restrict__ Wlv, const float* __restrict__ blv,
                       const float* __restrict__ eps, const float* __restrict__ We1,
                       const float* __restrict__ be1) {
    __shared__ float gv[Hh];
    __shared__ float zv[Zz];
    int t = threadIdx.x;
    float s = 0.f, s2 = 0.f;
    for (int i = 0; i < Nn; ++i) { float u = g_U[i*Hh + t]; s += u; s2 += u*u; }
    float m = s * (1.f/Nn);
    float v = s2 * (1.f/Nn) - m*m;
    float sc = g2[t] * rsqrtf(fmaxf(v, 0.f) + 1e-5f), bo = bt2[t];
    float gs = 0.f;
    for (int i = 0; i < Nn; ++i) {
        float u = g_U[i*Hh + t];
        gs += fmaxf((u - m)*sc + bo, 0.f);
    }
    gv[t] = gs * (1.f/Nn);
    __syncthreads();
    if (t < Zz) {
        float mu = bmu[t], lv = blv[t];
        for (int f = 0; f < Hh; ++f) { mu += gv[f]*Wmu[f*Zz + t]; lv += gv[f]*Wlv[f*Zz + t]; }
        lv = fminf(fmaxf(lv, -4.f), 4.f);
        zv[t] = mu + eps[t] * expf(0.5f * lv);
    }
    __syncthreads();
    float h = be1[t];
    for (int z = 0; z < Zz; ++z) h += zv[z] * We1[z*Hh + t];
    g_he[t] = fmaxf(h, 0.f);
}

// ============ launch 6: decoder logits -> B' -> node_sim -> 50x MPM =======
__global__ void __launch_bounds__(NT, 1) k_mpm(const float* __restrict__ We2,
                                               const float* __restrict__ be2,
                                               float* __restrict__ out) {
    extern __shared__ float sm[];
    float* Xs  = sm;                      // [Nn][XP]
    float* As  = Xs  + Nn*XP;             // [Nn][XP]
    float* Ms  = As  + Nn*XP;             // [AB][XP]
    float* Bs  = Ms  + AB*XP;             // [AB][Nn]
    float* dAs = Bs  + AB*Nn;             // [Nn]
    float* dBs = dAs + Nn;                // [8]
    float* red = dBs + 8;                 // [16]
    __shared__ float he[Hh];
    const int tid = threadIdx.x, cta = blockIdx.x;
    const int a0 = cta * AB;
    int epoch = 0;

    // static A' into SMEM (written by launch 1)
    for (int idx = tid; idx < Nn*Nn; idx += NT)
        As[(idx/Nn)*XP + (idx%Nn)] = g_A[idx];
    for (int k = tid; k < Hh; k += NT) he[k] = g_he[k];
    __syncthreads();

    // ---- decoder: 200 consecutive outputs per CTA ----
    {
        int o = cta*200 + tid;
        if (tid < 200 && o < OFFS) {
            float acc = be2[o];
            #pragma unroll 8
            for (int h = 0; h < Hh; ++h) acc += he[h] * We2[h*OFFS + o];
            float sg = 1.f / (1.f + expf(-acc));
            int i = 0, rem = o;
            while (rem >= (Nn-1) - i) { rem -= (Nn-1) - i; ++i; }
            int j = i + 1 + rem;
            g_B[i*Nn + j] = sg;
            g_B[j*Nn + i] = sg;
        }
    }
    // ---- barrier: B complete ----
    __syncthreads();
    ++epoch;
    if (tid == 0) {
        bar_arrive();
        while (bar_ld() < (unsigned)(NB*epoch)) { }
    }
    __syncthreads();

    // ---- B rows for this CTA's a-slice, degrees, node_sim ----
    if (tid < AB*Nn) {
        int r = tid / Nn, j = tid % Nn;
        Bs[r*Nn + j] = __ldcg(&g_B[(a0+r)*Nn + j]);
    }
    __syncthreads();
    if (tid < Nn) { float s = 1.f; for (int j = 0; j < Nn; ++j) s += As[tid*XP + j]; dAs[tid] = s; }
    if (tid < AB) { float s = 1.f; for (int j = 0; j < Nn; ++j) s += Bs[tid*Nn + j]; dBs[tid] = s; }
    __syncthreads();

    int i2 = 0, r2 = 0, r1 = 0, j1 = 0;
    float nsv = 0.f;
    if (tid < Nn*AB) {
        r1 = tid / Nn; j1 = tid - r1*Nn;      // step-1 mapping (a-row, j)
        i2 = tid / AB; r2 = tid - i2*AB;      // step-2 mapping (i, a-row)
        nsv = 1.f / (fabsf(dAs[i2] - dBs[r2]) + 1.f);
    }
    // X0 = 1/80 scaled by 2^7 -> 1.6 (max of X0 is 1/80, exp bits 120 -> scale 128)
    for (int idx = tid; idx < Nn*XP; idx += NT) Xs[idx] = 1.6f;
    __syncthreads();

    for (int it = 0; it < ITERS; ++it) {
        float* Xout = (it & 1) ? g_X0 : g_X1;
        if (it > 0) {
            const float2* Xin2 = (const float2*)((it & 1) ? g_X1 : g_X0);
            unsigned mb = __ldcg(&g_maxbits[it]);
            float scale = __uint_as_float((254u - ((mb >> 23) & 255u)) << 23);
            float2* Xs2 = (float2*)Xs;
            for (int g = tid; g < Nn*Nn/2; g += NT) {
                float2 v = __ldcg(&Xin2[g]);
                v.x *= scale; v.y *= scale;
                Xs2[(g/40)*(XP/2) + (g%40)] = v;
            }
            __syncthreads();
        }

        // step 1: M[r][j] = max_b B'[a0+r][b] * X[j][b]   (packed mul + scalar max)
        if (tid < Nn*AB) {
            const float2* Brow = (const float2*)(Bs + r1*Nn);
            const float2* Xrow = (const float2*)(Xs + j1*XP);
            float m0 = 0.f, m1 = 0.f;
            #pragma unroll
            for (int b = 0; b < Nn/2; ++b) {
                float2 bv = Brow[b], xv = Xrow[b];
                unsigned long long pa = *(const unsigned long long*)&bv;
                unsigned long long pb = *(const unsigned long long*)&xv;
                unsigned long long pp;
                asm("mul.rn.f32x2 %0, %1, %2;" : "=l"(pp) : "l"(pa), "l"(pb));
                float2 pv = *(float2*)&pp;
                m0 = fmaxf(m0, pv.x);
                m1 = fmaxf(m1, pv.y);
            }
            Ms[r1*XP + j1] = fmaxf(m0, m1);
        }
        __syncthreads();

        // step 2: Xn[i][a0+r] = ns*X[i][a0+r] + sum_j A'[i][j]*M[r][j]  (packed fma)
        float lmax = 0.f;
        if (tid < Nn*AB) {
            const float2* Arow = (const float2*)(As + i2*XP);
            const float2* Mrow = (const float2*)(Ms + r2*XP);
            unsigned long long acc2 = 0ull;
            #pragma unroll
            for (int b = 0; b < Nn/2; ++b) {
                float2 av = Arow[b], mv = Mrow[b];
                unsigned long long pa = *(const unsigned long long*)&av;
                unsigned long long pm = *(const unsigned long long*)&mv;
                asm("fma.rn.f32x2 %0, %1, %2, %0;" : "+l"(acc2) : "l"(pa), "l"(pm));
            }
            float2 av2 = *(float2*)&acc2;
            float acc = av2.x + av2.y + Xs[i2*XP + a0 + r2] * nsv;
            Xout[i2*Nn + a0 + r2] = acc;
            lmax = acc;
        }
        // CTA max-reduce -> one relaxed red.max + release arrive per CTA
        #pragma unroll
        for (int o = 16; o; o >>= 1) lmax = fmaxf(lmax, __shfl_xor_sync(0xffffffffu, lmax, o));
        if ((tid & 31) == 0) red[tid >> 5] = lmax;
        __syncthreads();
        ++epoch;
        if (tid == 0) {
            float bm = red[0];
            #pragma unroll
            for (int w = 1; w < NT/32; ++w) bm = fmaxf(bm, red[w]);
            red_max_relaxed(&g_maxbits[it + 1], __float_as_uint(bm));
            bar_arrive();
            if (it + 1 < ITERS || cta == 0) {
                while (bar_ld() < (unsigned)(NB*epoch)) { }
            }
        }
        __syncthreads();
    }

    // ---- final true L2 normalization (CTA 0 only; deterministic) ----
    if (cta == 0) {
        const float2* Xf = (const float2*)(((ITERS - 1) & 1) ? g_X0 : g_X1);
        float ss = 0.f;
        for (int g = tid; g < Nn*Nn/2; g += NT) {
            float2 v = __ldcg(&Xf[g]);
            ss += v.x*v.x + v.y*v.y;
        }
        #pragma unroll
        for (int o = 16; o; o >>= 1) ss += __shfl_xor_sync(0xffffffffu, ss, o);
        if ((tid & 31) == 0) red[tid >> 5] = ss;
        __syncthreads();
        if (tid == 0) {
            float tot = 0.f;
            for (int w = 0; w < NT/32; ++w) tot += red[w];
            red[0] = 1.f / sqrtf(tot);
        }
        __syncthreads();
        float inv = red[0];
        float2* out2 = (float2*)out;
        for (int g = tid; g < Nn*Nn/2; g += NT) {
            float2 v = __ldcg(&Xf[g]);
            v.x *= inv; v.y *= inv;
            out2[g] = v;
        }
    }
}

// ---------------- launch ----------------
extern "C" void kernel_launch(void* const* d_in, const int* in_sizes, int n_in,
                              void* d_out, int out_size) {
    const float* x   = (const float*)d_in[0];
    const int*   ei  = (const int*)  d_in[1];
    const int*   adj = (const int*)  d_in[2];
    const float* eps = (const float*)d_in[3];
    const float* W1  = (const float*)d_in[4];
    const float* b1  = (const float*)d_in[5];
    const float* g1  = (const float*)d_in[6];
    const float* bt1 = (const float*)d_in[7];
    const float* W2  = (const float*)d_in[8];
    const float* b2  = (const float*)d_in[9];
    const float* g2  = (const float*)d_in[10];
    const float* bt2 = (const float*)d_in[11];
    const float* Wmu = (const float*)d_in[12];
    const float* bmu = (const float*)d_in[13];
    const float* Wlv = (const float*)d_in[14];
    const float* blv = (const float*)d_in[15];
    const float* We1 = (const float*)d_in[16];
    const float* be1 = (const float*)d_in[17];
    const float* We2 = (const float*)d_in[18];
    const float* be2 = (const float*)d_in[19];
    // d_in[20..23] (Wn*, bn*) are dead: B's diagonal is overwritten with 1.

    k_setup_xw1<<<Nn, 256>>>(x, ei, adj, W1);
    k_agg<<<Nn, 256>>>(b1);
    k_bn_xw2<<<Nn, 256>>>(g1, bt1, W2);
    k_agg<<<Nn, 256>>>(b2);
    k_head<<<1, 256>>>(g2, bt2, Wmu, bmu, Wlv, blv, eps, We1, be1);

    size_t smem = (size_t)(Nn*XP*2 + AB*XP + AB*Nn + Nn + 8 + 16) * sizeof(float);
    cudaFuncSetAttribute((const void*)k_mpm,
                         cudaFuncAttributeMaxDynamicSharedMemorySize, (int)smem);
    k_mpm<<<NB, NT, smem>>>(We2, be2, (float*)d_out);
}

// round 8
// speedup vs baseline: 1.0060x; 1.0060x over previous
#include <cuda_runtime.h>

#define Nn 80
#define Fh 64
#define Hh 256
#define Zz 128
#define OFFS 3160
#define Eg 800
#define ITERS 50
#define NB 16
#define AB 5       // a-rows per CTA
#define NT 512
#define XP 82      // padded SMEM row stride (floats)

// ---------------- device scratch (static, allocation-free) ----------------
__device__ float g_Ag[Nn*Nn];
__device__ float g_T[Nn*Hh];
__device__ float g_U[Nn*Hh];
__device__ float g_he[Hh];
__device__ float g_B[Nn*Nn];
__device__ float g_A[Nn*Nn];
__device__ float g_XT[2][Nn*Nn];       // transposed X, double-buffered
__device__ float g_flag[ITERS][NB];    // per-iter per-CTA slice max (>0 when published)
__device__ unsigned g_bar;

// ---------------- sync primitives ----------------
__device__ __forceinline__ void bar_arrive() {
    asm volatile("red.release.gpu.add.u32 [%0], %1;" :: "l"(&g_bar), "r"(1u) : "memory");
}
__device__ __forceinline__ unsigned bar_ld() {
    unsigned v;
    asm volatile("ld.acquire.gpu.u32 %0, [%1];" : "=r"(v) : "l"(&g_bar) : "memory");
    return v;
}
__device__ __forceinline__ float ld_acq_f(const float* p) {
    float v;
    asm volatile("ld.acquire.gpu.global.f32 %0, [%1];" : "=f"(v) : "l"(p) : "memory");
    return v;
}
__device__ __forceinline__ void st_rel_f(float* p, float v) {
    asm volatile("st.release.gpu.global.f32 [%0], %1;" :: "l"(p), "f"(v) : "memory");
}

// ============ launch 1: setup (deg, Ag, A', B=0, flags=0) + x@W1 ==========
__global__ void k_setup_xw1(const float* __restrict__ x, const int* __restrict__ ei,
                            const int* __restrict__ adj, const float* __restrict__ W1) {
    __shared__ int   se[2*Eg];
    __shared__ int   cnt[Nn];
    __shared__ int   acnt[Nn];
    __shared__ float dinv[Nn];
    __shared__ float xr[Fh];
    int t = threadIdx.x, row = blockIdx.x;

    if (row == 0) {
        for (int idx = t; idx < ITERS*NB; idx += 256) ((float*)g_flag)[idx] = 0.f;
        if (t == 0) g_bar = 0u;
    }
    for (int e = t; e < 2*Eg; e += 256) se[e] = ei[e];
    if (t < Nn) { cnt[t] = 1; acnt[t] = 0; }
    for (int k = t; k < Fh; k += 256) xr[k] = x[row*Fh + k];
    __syncthreads();
    for (int e = t; e < Eg; e += 256) atomicAdd(&cnt[se[Eg+e]], 1);
    for (int e = t; e < Eg; e += 256)
        if (se[Eg+e] == row) atomicAdd(&acnt[se[e]], 1);
    __syncthreads();
    if (t < Nn) dinv[t] = rsqrtf((float)cnt[t]);
    __syncthreads();
    if (t < Nn) {
        float v = (float)acnt[t] * dinv[t] * dinv[row];
        if (t == row) v += dinv[row] * dinv[row];
        g_Ag[row*Nn + t] = v;
        g_A[row*Nn + t] = (row != t && ((adj[row*Nn+t] | adj[t*Nn+row]) != 0)) ? 1.f : 0.f;
        g_B[row*Nn + t] = 0.f;
    }
    float acc = 0.f;
    #pragma unroll 8
    for (int k = 0; k < Fh; ++k) acc += xr[k] * W1[k*Hh + t];
    g_T[row*Hh + t] = acc;
}

// ============ launches 2 & 4: U = Ag @ T + bias ===========================
__global__ void k_agg(const float* __restrict__ bias) {
    __shared__ float ar[Nn];
    int t = threadIdx.x, row = blockIdx.x;
    if (t < Nn) ar[t] = g_Ag[row*Nn + t];
    __syncthreads();
    float acc = bias[t];
    #pragma unroll 8
    for (int j = 0; j < Nn; ++j) acc += ar[j] * g_T[j*Hh + t];
    g_U[row*Hh + t] = acc;
}

// ============ launch 3: BN1 + ReLU + H@W2 =================================
__global__ void k_bn_xw2(const float* __restrict__ g1, const float* __restrict__ bt1,
                         const float* __restrict__ W2) {
    __shared__ float Hrow[Hh];
    int t = threadIdx.x, row = blockIdx.x;
    float s = 0.f, s2 = 0.f, urow = 0.f;
    for (int i = 0; i < Nn; ++i) {
        float u = g_U[i*Hh + t];
        s += u; s2 += u*u;
        if (i == row) urow = u;
    }
    float m = s * (1.f/Nn);
    float v = s2 * (1.f/Nn) - m*m;
    float sc = g1[t] * rsqrtf(fmaxf(v, 0.f) + 1e-5f);
    Hrow[t] = fmaxf((urow - m)*sc + bt1[t], 0.f);
    __syncthreads();
    float acc = 0.f;
    #pragma unroll 8
    for (int k = 0; k < Hh; ++k) acc += Hrow[k] * W2[k*Hh + t];
    g_T[row*Hh + t] = acc;
}

// ============ launch 5: BN2 + ReLU + pool + reparam + decoder hidden ======
__global__ void k_head(const float* __restrict__ g2, const float* __restrict__ bt2,
                       const float* __restrict__ Wmu, const float* __restrict__ bmu,
                       const float* __restrict__ Wlv, const float* __restrict__ blv,
                       const float* __restrict__ eps, const float* __restrict__ We1,
                       const float* __restrict__ be1) {
    __shared__ float gv[Hh];
    __shared__ float zv[Zz];
    int t = threadIdx.x;
    float s = 0.f, s2 = 0.f;
    for (int i = 0; i < Nn; ++i) { float u = g_U[i*Hh + t]; s += u; s2 += u*u; }
    float m = s * (1.f/Nn);
    float v = s2 * (1.f/Nn) - m*m;
    float sc = g2[t] * rsqrtf(fmaxf(v, 0.f) + 1e-5f), bo = bt2[t];
    float gs = 0.f;
    for (int i = 0; i < Nn; ++i) {
        float u = g_U[i*Hh + t];
        gs += fmaxf((u - m)*sc + bo, 0.f);
    }
    gv[t] = gs * (1.f/Nn);
    __syncthreads();
    if (t < Zz) {
        float mu = bmu[t], lv = blv[t];
        for (int f = 0; f < Hh; ++f) { mu += gv[f]*Wmu[f*Zz + t]; lv += gv[f]*Wlv[f*Zz + t]; }
        lv = fminf(fmaxf(lv, -4.f), 4.f);
        zv[t] = mu + eps[t] * expf(0.5f * lv);
    }
    __syncthreads();
    float h = be1[t];
    for (int z = 0; z < Zz; ++z) h += zv[z] * We1[z*Hh + t];
    g_he[t] = fmaxf(h, 0.f);
}

// ============ launch 6: decoder -> B' -> flag-synced MPM ==================
__global__ void __launch_bounds__(NT, 1) k_mpm(const float* __restrict__ We2,
                                               const float* __restrict__ be2,
                                               float* __restrict__ out) {
    __shared__ float As[Nn*XP];     // A' padded rows
    __shared__ float Bs[AB*Nn];     // own B' rows
    __shared__ float Ms[AB*Nn];     // step1 result
    __shared__ float dAs[Nn];
    __shared__ float red[NT/32];
    __shared__ float he[Hh];
    const int tid = threadIdx.x, cta = blockIdx.x;
    const int a0 = cta * AB;

    for (int k = tid; k < Hh; k += NT) he[k] = g_he[k];
    for (int idx = tid; idx < Nn*Nn; idx += NT)
        As[(idx/Nn)*XP + (idx%Nn)] = g_A[idx];
    __syncthreads();

    // ---- decoder: 200 consecutive outputs per CTA ----
    {
        int o = cta*200 + tid;
        if (tid < 200 && o < OFFS) {
            float acc = be2[o];
            #pragma unroll 8
            for (int h = 0; h < Hh; ++h) acc += he[h] * We2[h*OFFS + o];
            float sg = 1.f / (1.f + expf(-acc));
            int i = 0, rem = o;
            while (rem >= (Nn-1) - i) { rem -= (Nn-1) - i; ++i; }
            int j = i + 1 + rem;
            g_B[i*Nn + j] = sg;
            g_B[j*Nn + i] = sg;
        }
    }
    __syncthreads();
    // one-time global barrier: B complete
    if (tid == 0) { bar_arrive(); while (bar_ld() < (unsigned)NB) { } }
    __syncthreads();

    if (tid < AB*Nn) {
        int r = tid / Nn, j = tid % Nn;
        Bs[r*Nn + j] = __ldcg(&g_B[(a0+r)*Nn + j]);
    }
    __syncthreads();
    if (tid < Nn) { float s = 1.f; for (int j = 0; j < Nn; ++j) s += As[tid*XP + j]; dAs[tid] = s; }
    __syncthreads();

    // thread roles: 200 active workers
    const bool act = tid < AB*40;
    const int r  = tid / 40;        // a-row within slice (0..4)
    const int ii = tid % 40;        // step1: j-pair index; step2: output rows ii, ii+40
    float ns0 = 0.f, ns1 = 0.f;
    if (act) {
        float s = 1.f;
        for (int j = 0; j < Nn; ++j) s += Bs[r*Nn + j];
        ns0 = 1.f / (fabsf(dAs[ii]      - s) + 1.f);
        ns1 = 1.f / (fabsf(dAs[ii+40] - s) + 1.f);
    }

    float2* Ms2 = (float2*)Ms;

    for (int it = 0; it < ITERS; ++it) {
        float scale = 1.f;
        if (it == 0) {
            // X uniform (=1): M[r][j] = max_b B'[r][b]
            if (act) {
                float m = 0.f;
                #pragma unroll 8
                for (int b = 0; b < Nn; ++b) m = fmaxf(m, Bs[r*Nn + b]);
                float2 mm; mm.x = m; mm.y = m;
                Ms2[r*40 + ii] = mm;
            }
        } else {
            if (act) {
                // ---- poll all 16 producer flags; derive pow2 scale locally ----
                const float* flg = g_flag[it-1];
                float fv[NB];
                bool ok;
                do {
                    ok = true;
                    #pragma unroll
                    for (int p = 0; p < NB; ++p) { fv[p] = ld_acq_f(&flg[p]); ok &= (fv[p] != 0.f); }
                } while (!ok);
                float gmax = fv[0];
                #pragma unroll
                for (int p = 1; p < NB; ++p) gmax = fmaxf(gmax, fv[p]);
                unsigned mb = __float_as_uint(gmax);
                scale = __uint_as_float((254u - ((mb >> 23) & 255u)) << 23);

                // ---- step 1: M[r][2ii..2ii+1] = max_b B'[r][b] * XT[b][j] ----
                const float2* Xin = (const float2*)g_XT[(it-1)&1];
                float mx = 0.f, my = 0.f;
                #pragma unroll 10
                for (int b = 0; b < Nn; ++b) {
                    float  bb = Bs[r*Nn + b];
                    float2 xv = __ldcg(&Xin[b*40 + ii]);
                    mx = fmaxf(mx, bb * xv.x);
                    my = fmaxf(my, bb * xv.y);
                }
                float2 mm; mm.x = mx; mm.y = my;
                Ms2[r*40 + ii] = mm;
            }
        }
        __syncthreads();

        // ---- step 2: Xn[i][a0+r] = scale*(ns*X + sum_j A'[i][j]*M[r][j]) ----
        float lmax = 0.f;
        if (act) {
            float xoA = 1.f, xoB = 1.f;
            if (it > 0) {
                const float* Xp = g_XT[(it-1)&1];
                xoA = __ldcg(&Xp[(a0+r)*Nn + ii]);
                xoB = __ldcg(&Xp[(a0+r)*Nn + ii+40]);
            }
            const float2* A0 = (const float2*)(As + ii*XP);
            const float2* A1 = (const float2*)(As + (ii+40)*XP);
            const float2* Mr = Ms2 + r*40;
            float2 sA; sA.x = 0.f; sA.y = 0.f;
            float2 sB; sB.x = 0.f; sB.y = 0.f;
            #pragma unroll 8
            for (int b = 0; b < 40; ++b) {
                float2 m2 = Mr[b];
                float2 a0v = A0[b], a1v = A1[b];
                sA.x += a0v.x * m2.x; sA.y += a0v.y * m2.y;
                sB.x += a1v.x * m2.x; sB.y += a1v.y * m2.y;
            }
            float o0 = scale * (sA.x + sA.y + xoA * ns0);
            float o1 = scale * (sB.x + sB.y + xoB * ns1);
            float* XO = g_XT[it&1];
            XO[(a0+r)*Nn + ii]      = o0;
            XO[(a0+r)*Nn + ii + 40] = o1;
            lmax = fmaxf(o0, o1);
        }
        // ---- CTA max reduce + publish (release) ----
        #pragma unroll
        for (int o = 16; o; o >>= 1) lmax = fmaxf(lmax, __shfl_xor_sync(0xffffffffu, lmax, o));
        if ((tid & 31) == 0) red[tid >> 5] = lmax;
        __syncthreads();
        if (tid == 0) {
            float bm = red[0];
            #pragma unroll
            for (int w = 1; w < NT/32; ++w) bm = fmaxf(bm, red[w]);
            st_rel_f(&g_flag[it][cta], bm);
        }
        __syncthreads();   // also protects Ms/red WAR for next iteration
    }

    // ---- final: wait last flags, global L2 norm (identical in every CTA), write slice ----
    if (tid == 0) {
        const float* flg = g_flag[ITERS-1];
        bool ok;
        do {
            ok = true;
            #pragma unroll
            for (int p = 0; p < NB; ++p) ok &= (ld_acq_f(&flg[p]) != 0.f);
        } while (!ok);
    }
    __syncthreads();

    const float* Xf = g_XT[(ITERS-1)&1];
    const float2* Xf2 = (const float2*)Xf;
    float ss = 0.f;
    for (int g = tid; g < Nn*Nn/2; g += NT) {
        float2 v = __ldcg(&Xf2[g]);
        ss += v.x*v.x + v.y*v.y;
    }
    #pragma unroll
    for (int o = 16; o; o >>= 1) ss += __shfl_xor_sync(0xffffffffu, ss, o);
    if ((tid & 31) == 0) red[tid >> 5] = ss;
    __syncthreads();
    if (tid == 0) {
        float tot = 0.f;
        for (int w = 0; w < NT/32; ++w) tot += red[w];
        red[0] = 1.f / sqrtf(tot);
    }
    __syncthreads();
    float inv = red[0];
    for (int o = tid; o < AB*Nn; o += NT) {
        int rr = o / Nn, iw = o % Nn;
        out[iw*Nn + a0 + rr] = __ldcg(&Xf[(a0+rr)*Nn + iw]) * inv;
    }
}

// ---------------- launch ----------------
extern "C" void kernel_launch(void* const* d_in, const int* in_sizes, int n_in,
                              void* d_out, int out_size) {
    const float* x   = (const float*)d_in[0];
    const int*   ei  = (const int*)  d_in[1];
    const int*   adj = (const int*)  d_in[2];
    const float* eps = (const float*)d_in[3];
    const float* W1  = (const float*)d_in[4];
    const float* b1  = (const float*)d_in[5];
    const float* g1  = (const float*)d_in[6];
    const float* bt1 = (const float*)d_in[7];
    const float* W2  = (const float*)d_in[8];
    const float* b2  = (const float*)d_in[9];
    const float* g2  = (const float*)d_in[10];
    const float* bt2 = (const float*)d_in[11];
    const float* Wmu = (const float*)d_in[12];
    const float* bmu = (const float*)d_in[13];
    const float* Wlv = (const float*)d_in[14];
    const float* blv = (const float*)d_in[15];
    const float* We1 = (const float*)d_in[16];
    const float* be1 = (const float*)d_in[17];
    const float* We2 = (const float*)d_in[18];
    const float* be2 = (const float*)d_in[19];
    // d_in[20..23] (Wn*, bn*) are dead: B's diagonal is overwritten with 1.

    k_setup_xw1<<<Nn, 256>>>(x, ei, adj, W1);
    k_agg<<<Nn, 256>>>(b1);
    k_bn_xw2<<<Nn, 256>>>(g1, bt1, W2);
    k_agg<<<Nn, 256>>>(b2);
    k_head<<<1, 256>>>(g2, bt2, Wmu, bmu, Wlv, blv, eps, We1, be1);
    k_mpm<<<NB, NT>>>(We2, be2, (float*)d_out);
}

// round 9
// speedup vs baseline: 1.5261x; 1.5170x over previous
#include <cuda_runtime.h>

#define Nn 80
#define Fh 64
#define Hh 256
#define Zz 128
#define OFFS 3160
#define Eg 800
#define ITERS 50
#define NB 80      // CTAs in MPM: one X-row each
#define NT 320
#define BP 84      // padded B row stride

// ---------------- device scratch (static, allocation-free) ----------------
__device__ float g_Ag[Nn*Nn];
__device__ float g_T[Nn*Hh];
__device__ float g_U[Nn*Hh];
__device__ float g_he[Hh];
__device__ float g_B[Nn*Nn];
__device__ float g_A[Nn*Nn];
__device__ float g_M[2][Nn*Nn];        // exchanged quantity, double-buffered
__device__ float g_flag[ITERS][NB];    // per-iter per-CTA local X-max (nonzero = published)
__device__ float g_nrm[NB];
__device__ unsigned g_bar;

// ---------------- sync primitives ----------------
__device__ __forceinline__ void bar_arrive() {
    asm volatile("red.release.gpu.add.u32 [%0], %1;" :: "l"(&g_bar), "r"(1u) : "memory");
}
__device__ __forceinline__ unsigned bar_ld() {
    unsigned v;
    asm volatile("ld.acquire.gpu.u32 %0, [%1];" : "=r"(v) : "l"(&g_bar) : "memory");
    return v;
}
__device__ __forceinline__ float ld_acq_f(const float* p) {
    float v;
    asm volatile("ld.acquire.gpu.global.f32 %0, [%1];" : "=f"(v) : "l"(p) : "memory");
    return v;
}
__device__ __forceinline__ void st_rel_f(float* p, float v) {
    asm volatile("st.release.gpu.global.f32 [%0], %1;" :: "l"(p), "f"(v) : "memory");
}

// ============ launch 1: setup (deg, Ag, A', B=0, flags=0) + x@W1 ==========
__global__ void k_setup_xw1(const float* __restrict__ x, const int* __restrict__ ei,
                            const int* __restrict__ adj, const float* __restrict__ W1) {
    __shared__ int   se[2*Eg];
    __shared__ int   cnt[Nn];
    __shared__ int   acnt[Nn];
    __shared__ float dinv[Nn];
    __shared__ float xr[Fh];
    int t = threadIdx.x, row = blockIdx.x;

    if (row == 0) {
        for (int idx = t; idx < ITERS*NB; idx += 256) ((float*)g_flag)[idx] = 0.f;
        if (t < NB) g_nrm[t] = 0.f;
        if (t == 0) g_bar = 0u;
    }
    for (int e = t; e < 2*Eg; e += 256) se[e] = ei[e];
    if (t < Nn) { cnt[t] = 1; acnt[t] = 0; }
    for (int k = t; k < Fh; k += 256) xr[k] = x[row*Fh + k];
    __syncthreads();
    for (int e = t; e < Eg; e += 256) atomicAdd(&cnt[se[Eg+e]], 1);
    for (int e = t; e < Eg; e += 256)
        if (se[Eg+e] == row) atomicAdd(&acnt[se[e]], 1);
    __syncthreads();
    if (t < Nn) dinv[t] = rsqrtf((float)cnt[t]);
    __syncthreads();
    if (t < Nn) {
        float v = (float)acnt[t] * dinv[t] * dinv[row];
        if (t == row) v += dinv[row] * dinv[row];
        g_Ag[row*Nn + t] = v;
        g_A[row*Nn + t] = (row != t && ((adj[row*Nn+t] | adj[t*Nn+row]) != 0)) ? 1.f : 0.f;
        g_B[row*Nn + t] = 0.f;
    }
    float acc = 0.f;
    #pragma unroll 16
    for (int k = 0; k < Fh; ++k) acc += xr[k] * W1[k*Hh + t];
    g_T[row*Hh + t] = acc;
}

// ============ launches 2 & 4: U = Ag @ T + bias ===========================
__global__ void k_agg(const float* __restrict__ bias) {
    __shared__ float ar[Nn];
    int t = threadIdx.x, row = blockIdx.x;
    if (t < Nn) ar[t] = g_Ag[row*Nn + t];
    __syncthreads();
    float acc = bias[t];
    #pragma unroll 16
    for (int j = 0; j < Nn; ++j) acc += ar[j] * g_T[j*Hh + t];
    g_U[row*Hh + t] = acc;
}

// ============ launch 3: BN1 + ReLU + H@W2 =================================
__global__ void k_bn_xw2(const float* __restrict__ g1, const float* __restrict__ bt1,
                         const float* __restrict__ W2) {
    __shared__ float Hrow[Hh];
    int t = threadIdx.x, row = blockIdx.x;
    float s = 0.f, s2 = 0.f, urow = 0.f;
    #pragma unroll 16
    for (int i = 0; i < Nn; ++i) {
        float u = g_U[i*Hh + t];
        s += u; s2 += u*u;
        if (i == row) urow = u;
    }
    float m = s * (1.f/Nn);
    float v = s2 * (1.f/Nn) - m*m;
    float sc = g1[t] * rsqrtf(fmaxf(v, 0.f) + 1e-5f);
    Hrow[t] = fmaxf((urow - m)*sc + bt1[t], 0.f);
    __syncthreads();
    float acc = 0.f;
    #pragma unroll 16
    for (int k = 0; k < Hh; ++k) acc += Hrow[k] * W2[k*Hh + t];
    g_T[row*Hh + t] = acc;
}

// ============ launch 5: BN2 + ReLU + pool + reparam + decoder hidden ======
__global__ void k_head(const float* __restrict__ g2, const float* __restrict__ bt2,
                       const float* __restrict__ Wmu, const float* __restrict__ bmu,
                       const float* __restrict__ Wlv, const float* __restrict__ blv,
                       const float* __restrict__ eps, const float* __restrict__ We1,
                       const float* __restrict__ be1) {
    __shared__ float gv[Hh];
    __shared__ float zv[Zz];
    int t = threadIdx.x;
    float s = 0.f, s2 = 0.f;
    #pragma unroll 16
    for (int i = 0; i < Nn; ++i) { float u = g_U[i*Hh + t]; s += u; s2 += u*u; }
    float m = s * (1.f/Nn);
    float v = s2 * (1.f/Nn) - m*m;
    float sc = g2[t] * rsqrtf(fmaxf(v, 0.f) + 1e-5f), bo = bt2[t];
    float gs = 0.f;
    #pragma unroll 16
    for (int i = 0; i < Nn; ++i) {
        float u = g_U[i*Hh + t];
        gs += fmaxf((u - m)*sc + bo, 0.f);
    }
    gv[t] = gs * (1.f/Nn);
    __syncthreads();
    if (t < Zz) {
        float mu = bmu[t], lv = blv[t];
        #pragma unroll 16
        for (int f = 0; f < Hh; ++f) { mu += gv[f]*Wmu[f*Zz + t]; lv += gv[f]*Wlv[f*Zz + t]; }
        lv = fminf(fmaxf(lv, -4.f), 4.f);
        zv[t] = mu + eps[t] * expf(0.5f * lv);
    }
    __syncthreads();
    float h = be1[t];
    #pragma unroll 16
    for (int z = 0; z < Zz; ++z) h += zv[z] * We1[z*Hh + t];
    g_he[t] = fmaxf(h, 0.f);
}

// ============ launch 6: decoder -> B' -> M-exchange MPM (X stays local) ===
__global__ void __launch_bounds__(NT, 1) k_mpm(const float* __restrict__ We2,
                                               const float* __restrict__ be2,
                                               float* __restrict__ out) {
    __shared__ float Bs[Nn*BP];   // full B', padded rows
    __shared__ float he[Hh];
    __shared__ float Xs[BP];      // own X row (local across ALL iterations)
    __shared__ float As[BP];      // own A' row
    __shared__ float nss[BP];     // own node_sim row
    __shared__ float dBs[BP];
    __shared__ float p1[Nn*4];    // 4-way partials
    __shared__ float red[8];
    __shared__ float sg[4];       // [0]=scale / inv-norm, [1]=dA
    const int t = threadIdx.x, c = blockIdx.x;

    for (int k = t; k < Hh; k += NT) he[k] = g_he[k];
    __syncthreads();

    // ---- decoder: 40 outputs per CTA, 4 threads per output ----
    if (t < 160) {
        int ol = t >> 2, q = t & 3;
        int o = c*40 + ol;
        float acc = 0.f;
        if (o < OFFS) {
            #pragma unroll 16
            for (int h = q*64; h < q*64 + 64; ++h) acc += he[h] * We2[h*OFFS + o];
        }
        p1[ol*4 + q] = acc;
    }
    __syncthreads();
    if (t < 40) {
        int o = c*40 + t;
        if (o < OFFS) {
            float4 pv = *(float4*)&p1[t*4];
            float acc = pv.x + pv.y + pv.z + pv.w + be2[o];
            float sgm = 1.f / (1.f + expf(-acc));
            int i = 0, rem = o;
            while (rem >= (Nn-1) - i) { rem -= (Nn-1) - i; ++i; }
            int j = i + 1 + rem;
            g_B[i*Nn + j] = sgm;
            g_B[j*Nn + i] = sgm;
        }
    }
    __syncthreads();
    // ---- one-time global barrier: B complete ----
    if (t == 0) { bar_arrive(); while (bar_ld() < (unsigned)NB) { } }
    __syncthreads();

    // ---- static operands ----
    for (int idx = t; idx < Nn*Nn; idx += NT) {
        int r = idx / Nn, cc = idx % Nn;
        Bs[r*BP + cc] = __ldcg(&g_B[idx]);
    }
    if (t < Nn) { As[t] = __ldcg(&g_A[c*Nn + t]); Xs[t] = 1.f; }
    __syncthreads();
    if (t < Nn) {
        float s = 1.f;
        #pragma unroll 10
        for (int j = 0; j < Nn; ++j) s += Bs[t*BP + j];
        dBs[t] = s;
    }
    if (t == 0) {
        float s = 1.f;
        #pragma unroll 10
        for (int j = 0; j < Nn; ++j) s += As[j];
        sg[1] = s;
        red[0] = 1.f; red[1] = 0.f; red[2] = 0.f;   // X^0 max = 1
    }
    __syncthreads();
    if (t < Nn) nss[t] = 1.f / (fabsf(sg[1] - dBs[t]) + 1.f);
    __syncthreads();

    const int a = t % Nn;      // 0..79
    const int h = t / Nn;      // 0..3 (b/j quarter)

    for (int it = 0; it < ITERS; ++it) {
        float* Mb = g_M[it & 1];

        // ---- step 1 partial: max over b-quarter of B[a][b]*X[b] ----
        {
            const float4* Bq = (const float4*)&Bs[a*BP + 20*h];
            const float4* Xq = (const float4*)&Xs[20*h];
            float m = 0.f;
            #pragma unroll
            for (int k = 0; k < 5; ++k) {
                float4 b4 = Bq[k], x4 = Xq[k];
                m = fmaxf(m, b4.x*x4.x); m = fmaxf(m, b4.y*x4.y);
                m = fmaxf(m, b4.z*x4.z); m = fmaxf(m, b4.w*x4.w);
            }
            p1[a*4 + h] = m;
        }
        __syncthreads();
        if (t < Nn) {
            float4 pv = *(float4*)&p1[t*4];
            Mb[t*Nn + c] = fmaxf(fmaxf(pv.x, pv.y), fmaxf(pv.z, pv.w));
        }
        __syncthreads();

        // ---- publish flag (value = local X^it max), poll all 80 ----
        if (t == 0) {
            float lm = fmaxf(red[0], fmaxf(red[1], red[2]));
            st_rel_f(&g_flag[it][c], lm);
        }
        if (t < 32) {
            const float* fl = g_flag[it];
            float v0, v1, v2;
            bool ok;
            do {
                v0 = ld_acq_f(&fl[t]);
                v1 = ld_acq_f(&fl[t + 32]);
                v2 = (t < 16) ? ld_acq_f(&fl[t + 64]) : 1.f;
                ok = (v0 != 0.f) && (v1 != 0.f) && (v2 != 0.f);
            } while (__ballot_sync(0xffffffffu, ok) != 0xffffffffu);
            float gm = fmaxf(v0, v1);
            if (t < 16) gm = fmaxf(gm, v2);
            #pragma unroll
            for (int o2 = 16; o2; o2 >>= 1) gm = fmaxf(gm, __shfl_xor_sync(0xffffffffu, gm, o2));
            if (t == 0) {
                unsigned mb = __float_as_uint(gm);
                sg[0] = __uint_as_float((254u - ((mb >> 23) & 255u)) << 23);
            }
        }
        __syncthreads();

        // ---- step 2 partial: sum over j-quarter of A[j]*M[a][j] ----
        {
            const float4* Mq = (const float4*)&Mb[a*Nn + 20*h];
            const float4* Aq = (const float4*)&As[20*h];
            float s0 = 0.f, s1 = 0.f, s2 = 0.f, s3 = 0.f;
            #pragma unroll
            for (int k = 0; k < 5; ++k) {
                float4 m4 = __ldcg(&Mq[k]);
                float4 a4 = Aq[k];
                s0 += m4.x*a4.x; s1 += m4.y*a4.y;
                s2 += m4.z*a4.z; s3 += m4.w*a4.w;
            }
            p1[a*4 + h] = (s0 + s1) + (s2 + s3);
        }
        __syncthreads();

        // ---- combine, scale, update local X ----
        float lmax = 0.f;
        if (t < Nn) {
            float4 pv = *(float4*)&p1[t*4];
            float xn = sg[0] * ((pv.x + pv.y + pv.z + pv.w) + nss[t] * Xs[t]);
            Xs[t] = xn;
            lmax = xn;
        }
        #pragma unroll
        for (int o2 = 16; o2; o2 >>= 1) lmax = fmaxf(lmax, __shfl_xor_sync(0xffffffffu, lmax, o2));
        if ((t & 31) == 0 && t < 96) red[t >> 5] = lmax;
        __syncthreads();
    }

    // ---- final global L2 norm (deterministic: same order everywhere) ----
    if (t < Nn) p1[t] = Xs[t] * Xs[t];
    __syncthreads();
    if (t == 0) {
        float ss2 = 0.f;
        #pragma unroll 16
        for (int k = 0; k < Nn; ++k) ss2 += p1[k];
        st_rel_f(&g_nrm[c], ss2);
    }
    if (t < 32) {
        bool ok;
        do {
            float v0 = ld_acq_f(&g_nrm[t]);
            float v1 = ld_acq_f(&g_nrm[t + 32]);
            float v2 = (t < 16) ? ld_acq_f(&g_nrm[t + 64]) : 1.f;
            ok = (v0 != 0.f) && (v1 != 0.f) && (v2 != 0.f);
        } while (__ballot_sync(0xffffffffu, ok) != 0xffffffffu);
    }
    __syncthreads();
    if (t == 0) {
        float tot = 0.f;
        #pragma unroll 16
        for (int k = 0; k < Nn; ++k) tot += __ldcg(&g_nrm[k]);
        sg[0] = 1.f / sqrtf(tot);
    }
    __syncthreads();
    if (t < Nn) out[c*Nn + t] = Xs[t] * sg[0];
}

// ---------------- launch ----------------
extern "C" void kernel_launch(void* const* d_in, const int* in_sizes, int n_in,
                              void* d_out, int out_size) {
    const float* x   = (const float*)d_in[0];
    const int*   ei  = (const int*)  d_in[1];
    const int*   adj = (const int*)  d_in[2];
    const float* eps = (const float*)d_in[3];
    const float* W1  = (const float*)d_in[4];
    const float* b1  = (const float*)d_in[5];
    const float* g1  = (const float*)d_in[6];
    const float* bt1 = (const float*)d_in[7];
    const float* W2  = (const float*)d_in[8];
    const float* b2  = (const float*)d_in[9];
    const float* g2  = (const float*)d_in[10];
    const float* bt2 = (const float*)d_in[11];
    const float* Wmu = (const float*)d_in[12];
    const float* bmu = (const float*)d_in[13];
    const float* Wlv = (const float*)d_in[14];
    const float* blv = (const float*)d_in[15];
    const float* We1 = (const float*)d_in[16];
    const float* be1 = (const float*)d_in[17];
    const float* We2 = (const float*)d_in[18];
    const float* be2 = (const float*)d_in[19];
    // d_in[20..23] (Wn*, bn*) are dead: B's diagonal is overwritten with 1.

    k_setup_xw1<<<Nn, 256>>>(x, ei, adj, W1);
    k_agg<<<Nn, 256>>>(b1);
    k_bn_xw2<<<Nn, 256>>>(g1, bt1, W2);
    k_agg<<<Nn, 256>>>(b2);
    k_head<<<1, 256>>>(g2, bt2, Wmu, bmu, Wlv, blv, eps, We1, be1);
    k_mpm<<<NB, NT>>>(We2, be2, (float*)d_out);
}